// round 11
// baseline (speedup 1.0000x reference)
#include <cuda_runtime.h>
#include <cuda_fp16.h>
#include <cuda_bf16.h>
#include <cstdint>

// ---------------------------------------------------------------------------
// InversionModel R11: R10 with the cp.async visibility race FIXED:
// single __syncthreads per 64-K tile, placed AFTER wait_group; all reads of
// the new stage happen after it. BK=64, 3 stages, K padded to 6464.
// ---------------------------------------------------------------------------

#define BM 128
#define BN 128
#define BK 64                  // halves per K tile
#define STAGES 3
#define ROWB 144               // smem bytes per row: 128 data + 16 pad
#define M_DIM 2048
#define N_DIM 6432
#define K_DIM 6432
#define KP    6464             // K padded: 101 * 64
#define STAGE_BYTES ((BM + BN) * ROWB)            // 36864
#define SMEM_BYTES  (STAGES * STAGE_BYTES)        // 110592

#define FE_BLOCKS 6144                            // 2048 batches x 3 scales
#define NWP ((long long)N_DIM * KP)               // padded weight elems
#define CONV_BLOCKS ((int)((NWP + 1023) / 1024))  // 128 thr x 8 elems

// Scratch (static device arrays; no allocation allowed)
__device__ __align__(16) __half g_act0[(size_t)M_DIM * KP];
__device__ __align__(16) __half g_act1[(size_t)M_DIM * KP];
__device__ __align__(16) __half g_wh[(size_t)N_DIM * KP];

// ------------------------------ helpers ------------------------------------

__device__ __forceinline__ void cp16(void* dst, const void* src, bool pred) {
    uint32_t s = (uint32_t)__cvta_generic_to_shared(dst);
    int sz = pred ? 16 : 0;
    asm volatile("cp.async.cg.shared.global [%0], [%1], 16, %2;\n"
                 :: "r"(s), "l"(src), "r"(sz));
}

__device__ __forceinline__ void mma16816(float* c, const uint32_t* a, const uint32_t* b) {
    asm volatile(
        "mma.sync.aligned.m16n8k16.row.col.f32.f16.f16.f32 "
        "{%0,%1,%2,%3}, {%4,%5,%6,%7}, {%8,%9}, {%0,%1,%2,%3};\n"
        : "+f"(c[0]), "+f"(c[1]), "+f"(c[2]), "+f"(c[3])
        : "r"(a[0]), "r"(a[1]), "r"(a[2]), "r"(a[3]), "r"(b[0]), "r"(b[1]));
}

__device__ __forceinline__ void ldsm4(uint32_t& r0, uint32_t& r1, uint32_t& r2,
                                      uint32_t& r3, uint32_t addr) {
    asm volatile("ldmatrix.sync.aligned.m8n8.x4.shared.b16 {%0,%1,%2,%3}, [%4];\n"
                 : "=r"(r0), "=r"(r1), "=r"(r2), "=r"(r3) : "r"(addr));
}

// ----------------- fused prep: frontend + weight convert --------------------

__global__ void prep_kernel(const float* __restrict__ x,
                            const float* __restrict__ w1, const float* __restrict__ b1,
                            const float* __restrict__ w2, const float* __restrict__ b2,
                            __half* __restrict__ f, __half* __restrict__ f2,
                            const float* __restrict__ wl, __half* __restrict__ wh) {
    if (blockIdx.x >= FE_BLOCKS) {
        long long idx = (long long)(blockIdx.x - FE_BLOCKS) * 128 + threadIdx.x;
        const long long total = NWP / 8;
        if (idx < total) {
            int r  = (int)(idx / (KP / 8));
            int c0 = (int)(idx % (KP / 8)) * 8;
            uint4 outv = make_uint4(0, 0, 0, 0);
            if (c0 < K_DIM) {      // 6432 % 8 == 0: group fully in or fully pad
                const float* p = wl + (size_t)r * K_DIM + c0;
                float4 a = *(const float4*)p;
                float4 b = *(const float4*)(p + 4);
                __half2 h0 = __floats2half2_rn(a.x, a.y);
                __half2 h1 = __floats2half2_rn(a.z, a.w);
                __half2 h2 = __floats2half2_rn(b.x, b.y);
                __half2 h3 = __floats2half2_rn(b.z, b.w);
                outv = make_uint4(*(uint32_t*)&h0, *(uint32_t*)&h1,
                                  *(uint32_t*)&h2, *(uint32_t*)&h3);
            }
            *(uint4*)(wh + (size_t)r * KP + c0) = outv;
        }
        return;
    }

    int b = blockIdx.x & 2047;
    int sidx = blockIdx.x >> 11;     // 0,1,2 -> s = 1,2,4
    int s = 1 << sidx;
    int Lc = 480 >> sidx;
    int off = (sidx == 0) ? 0 : (sidx == 1 ? 117 : 174);

    __shared__ float xc[4 * 480];
    __shared__ float p1[16 * 238 + 2];   // +2: harmless OOB window read guard
    __shared__ float w1s[320], w2s[2560];
    __shared__ float b1s[16], b2s[32];

    int tid = threadIdx.x;           // 128 threads
    for (int i = tid; i < 320; i += 128) w1s[i] = w1[i];
    for (int i = tid; i < 2560; i += 128) w2s[i] = w2[i];
    if (tid < 16) b1s[tid] = b1[tid];
    if (tid < 32) b2s[tid] = b2[tid];

    // zero K-pad cols of both activation buffers
    if (sidx == 0 && tid < 32) {
        f [(size_t)b * KP + K_DIM + tid] = __float2half_rn(0.f);
        f2[(size_t)b * KP + K_DIM + tid] = __float2half_rn(0.f);
    }

    // coarse grain into smem
    const float* xb = x + (size_t)b * 4 * 480;
    float inv_s = 1.0f / (float)s;
    for (int i = tid; i < 4 * Lc; i += 128) {
        int c = i / Lc, p = i % Lc;
        float sum = 0.f;
        for (int j = 0; j < s; ++j) sum += xb[c * 480 + p * s + j];
        xc[c * Lc + p] = sum * inv_s;
    }
    __syncthreads();

    // conv1 + relu + pool
    int L1p = (Lc - 4) >> 1;         // 238 / 118 / 58
    {
        int o = tid & 15, ch = tid >> 4;
        float w1r[20];
        #pragma unroll
        for (int i = 0; i < 20; ++i) w1r[i] = w1s[o * 20 + i];
        float b1r = b1s[o];
        for (int q = ch; q < L1p; q += 8) {
            float a0 = b1r, a1 = b1r;
            #pragma unroll
            for (int c = 0; c < 4; ++c) {
                const float2* xp = (const float2*)&xc[c * Lc + 2 * q];
                float2 v0 = xp[0], v1 = xp[1], v2 = xp[2];
                const float* w = &w1r[c * 5];
                a0 = fmaf(v0.x, w[0], a0);
                a0 = fmaf(v0.y, w[1], a0);
                a0 = fmaf(v1.x, w[2], a0);
                a0 = fmaf(v1.y, w[3], a0);
                a0 = fmaf(v2.x, w[4], a0);
                a1 = fmaf(v0.y, w[0], a1);
                a1 = fmaf(v1.x, w[1], a1);
                a1 = fmaf(v1.y, w[2], a1);
                a1 = fmaf(v2.x, w[3], a1);
                a1 = fmaf(v2.y, w[4], a1);
            }
            p1[o * L1p + q] = fmaxf(fmaxf(a0, a1), 0.f);
        }
    }
    __syncthreads();

    // conv2 + relu + pool (q-pair window reuse, 4 chains)
    int L2 = (L1p - 4) >> 1;         // 117 / 57 / 27
    {
        int o2 = tid & 31, ch2 = tid >> 5;
        float w2r[80];
        #pragma unroll
        for (int i = 0; i < 80; ++i) w2r[i] = w2s[o2 * 80 + i];
        float b2r = b2s[o2];
        __half* fb = f + (size_t)b * KP;
        for (int q0 = 2 * ch2; q0 < L2; q0 += 8) {
            bool has2 = (q0 + 1) < L2;
            float a00 = b2r, a01 = b2r, a10 = b2r, a11 = b2r;
            #pragma unroll
            for (int c1 = 0; c1 < 16; ++c1) {
                const float2* pp = (const float2*)&p1[c1 * L1p + 2 * q0];
                float2 v0 = pp[0], v1 = pp[1], v2 = pp[2], v3 = pp[3];
                const float* w = &w2r[c1 * 5];
                a00 = fmaf(v0.x, w[0], a00);
                a00 = fmaf(v0.y, w[1], a00);
                a00 = fmaf(v1.x, w[2], a00);
                a00 = fmaf(v1.y, w[3], a00);
                a00 = fmaf(v2.x, w[4], a00);
                a01 = fmaf(v0.y, w[0], a01);
                a01 = fmaf(v1.x, w[1], a01);
                a01 = fmaf(v1.y, w[2], a01);
                a01 = fmaf(v2.x, w[3], a01);
                a01 = fmaf(v2.y, w[4], a01);
                a10 = fmaf(v1.x, w[0], a10);
                a10 = fmaf(v1.y, w[1], a10);
                a10 = fmaf(v2.x, w[2], a10);
                a10 = fmaf(v2.y, w[3], a10);
                a10 = fmaf(v3.x, w[4], a10);
                a11 = fmaf(v1.y, w[0], a11);
                a11 = fmaf(v2.x, w[1], a11);
                a11 = fmaf(v2.y, w[2], a11);
                a11 = fmaf(v3.x, w[3], a11);
                a11 = fmaf(v3.y, w[4], a11);
            }
            fb[o2 * 201 + off + q0] = __float2half_rn(fmaxf(fmaxf(a00, a01), 0.f));
            if (has2)
                fb[o2 * 201 + off + q0 + 1] = __float2half_rn(fmaxf(fmaxf(a10, a11), 0.f));
        }
    }
}

// ------------------------------- GEMM --------------------------------------
// 128x128x64 tiles, 4 warps (2x2), warp tile 64x64, 3 smem stages,
// ONE wait_group + __syncthreads per tile, all new-stage reads after it.

extern __shared__ __half dynsmem[];

__global__ __launch_bounds__(128, 2)
void gemm_relu_kernel(const __half* __restrict__ A, const __half* __restrict__ W,
                      const float* __restrict__ bias, __half* __restrict__ Out) {
    char* smem_c = (char*)dynsmem;

    const int tid = threadIdx.x;
    const int bm = blockIdx.y * BM;
    const int bn = blockIdx.x * BN;
    const int warp = tid >> 5, lane = tid & 31;
    const int wm = (warp >> 1) * 64;     // 0 or 64
    const int wn = (warp & 1) * 64;      // 0 or 64
    const int g = lane >> 2, tg = lane & 3;

    const int lr8 = tid >> 3;            // 0..15
    const int cbh = (tid & 7) * 8;       // halves offset 0..56

    const __half* Ag = A + (size_t)(bm + lr8) * KP + cbh;
    const __half* Wg = W + (size_t)(bn + lr8) * KP + cbh;
    const int limit = N_DIM - bn;
    bool bvm[8];
    #pragma unroll
    for (int i = 0; i < 8; ++i) bvm[i] = (lr8 + 16 * i) < limit;

#define LOAD_STAGE(slot, k0) do {                                             \
        char* _s  = smem_c + (slot) * STAGE_BYTES;                            \
        char* _sb = _s + BM * ROWB;                                           \
        _Pragma("unroll")                                                     \
        for (int _i = 0; _i < 8; ++_i)                                        \
            cp16(_s + (lr8 + 16 * _i) * ROWB + (cbh * 2),                     \
                 Ag + (size_t)(16 * _i) * KP + (k0), true);                   \
        _Pragma("unroll")                                                     \
        for (int _i = 0; _i < 8; ++_i)                                        \
            cp16(_sb + (lr8 + 16 * _i) * ROWB + (cbh * 2),                    \
                 Wg + (bvm[_i] ? (size_t)(16 * _i) * KP : 0) + (k0), bvm[_i]);\
    } while (0)

    const uint32_t sU = (uint32_t)__cvta_generic_to_shared(smem_c);
    const uint32_t a_off = (uint32_t)((wm + (lane & 15)) * ROWB + (lane >> 4) * 16);
    const uint32_t b_off = (uint32_t)(BM * ROWB
                                      + (wn + (lane >> 4) * 8 + (lane & 7)) * ROWB
                                      + ((lane >> 3) & 1) * 16);

#define LD_FRAGS(buf, ksb) do {                                                \
        _Pragma("unroll")                                                      \
        for (int _mt = 0; _mt < 4; ++_mt)                                      \
            ldsm4(afr[buf][_mt][0], afr[buf][_mt][1], afr[buf][_mt][2],        \
                  afr[buf][_mt][3], aS + (ksb) + _mt * 16 * ROWB);             \
        _Pragma("unroll")                                                      \
        for (int _p = 0; _p < 4; ++_p)                                         \
            ldsm4(bfr[buf][2 * _p][0], bfr[buf][2 * _p][1],                    \
                  bfr[buf][2 * _p + 1][0], bfr[buf][2 * _p + 1][1],            \
                  bS + (ksb) + _p * 16 * ROWB);                                \
    } while (0)

#define MMA_BATCH(buf) do {                                                    \
        _Pragma("unroll")                                                      \
        for (int _mt = 0; _mt < 4; ++_mt)                                      \
            _Pragma("unroll")                                                  \
            for (int _nt = 0; _nt < 8; ++_nt)                                  \
                mma16816(acc[_mt][_nt], afr[buf][_mt], bfr[buf][_nt]);         \
    } while (0)

    float acc[4][8][4];
    #pragma unroll
    for (int mt = 0; mt < 4; ++mt)
        #pragma unroll
        for (int nt = 0; nt < 8; ++nt)
            #pragma unroll
            for (int i = 0; i < 4; ++i) acc[mt][nt][i] = 0.f;

    uint32_t afr[2][4][4], bfr[2][8][2];

    // prologue: stages 0,1 hold tiles 0,1
    LOAD_STAGE(0, 0);
    asm volatile("cp.async.commit_group;\n");
    LOAD_STAGE(1, BK);
    asm volatile("cp.async.commit_group;\n");
    asm volatile("cp.async.wait_group 1;\n");   // own part of tile 0 done
    __syncthreads();                            // ALL parts of tile 0 visible

    uint32_t aS = sU + a_off;                   // stage 0
    uint32_t bS = sU + b_off;
    LD_FRAGS(0, 0);                             // tile 0, ks0

    const int NT = KP / BK;   // 101
    int st = 0;
    #pragma unroll 1
    for (int kt = 0; kt < NT; ++kt) {
        // All reads of stage st (tile kt) happen BEFORE this tile's sync.
        LD_FRAGS(1, 32);      // ks1
        MMA_BATCH(0);         // ks0
        LD_FRAGS(0, 64);      // ks2
        MMA_BATCH(1);         // ks1
        LD_FRAGS(1, 96);      // ks3
        MMA_BATCH(0);         // ks2

        // Write tile kt+2 into slot (st+2)%3 (held tile kt-1; its reads all
        // preceded iteration kt-1's end-of-loop __syncthreads).
        int knext = kt + 2;
        if (knext < NT) {
            int sl = st + 2; if (sl >= STAGES) sl -= STAGES;
            LOAD_STAGE(sl, knext * BK);
        }
        asm volatile("cp.async.commit_group;\n");

        MMA_BATCH(1);         // ks3 (no smem reads; overlaps wait below)

        asm volatile("cp.async.wait_group 1;\n");   // own tile kt+1 done
        __syncthreads();                            // EVERYONE's tile kt+1 done

        int st1 = st + 1; if (st1 >= STAGES) st1 -= STAGES;
        aS = sU + (uint32_t)(st1 * STAGE_BYTES) + a_off;
        bS = sU + (uint32_t)(st1 * STAGE_BYTES) + b_off;
        LD_FRAGS(0, 0);       // next tile ks0 (garbage on last iter, unused)
        st = st1;
    }

    // Epilogue: bias + relu + fp16 store (row stride KP)
    #pragma unroll
    for (int mt = 0; mt < 4; ++mt) {
        int row = bm + wm + mt * 16 + g;
        #pragma unroll
        for (int nt = 0; nt < 8; ++nt) {
            int col = bn + wn + nt * 8 + tg * 2;
            if (col < N_DIM) {
                float2 bb = *(const float2*)(bias + col);
                float v0a = fmaxf(acc[mt][nt][0] + bb.x, 0.f);
                float v1a = fmaxf(acc[mt][nt][1] + bb.y, 0.f);
                float v2a = fmaxf(acc[mt][nt][2] + bb.x, 0.f);
                float v3a = fmaxf(acc[mt][nt][3] + bb.y, 0.f);
                *(__half2*)(Out + (size_t)row * KP + col)       = __floats2half2_rn(v0a, v1a);
                *(__half2*)(Out + (size_t)(row + 8) * KP + col) = __floats2half2_rn(v2a, v3a);
            }
        }
    }
#undef LOAD_STAGE
#undef LD_FRAGS
#undef MMA_BATCH
}

// ------------------------------- head --------------------------------------

__global__ void head_kernel(const __half* __restrict__ f, const float* __restrict__ wo,
                            const float* __restrict__ bo, float* __restrict__ out) {
    int b = blockIdx.x;
    int w = threadIdx.x >> 5;        // 0..4
    int lane = threadIdx.x & 31;
    const __half* fb = f + (size_t)b * KP;
    const float* wr = wo + (size_t)w * N_DIM;
    float acc = 0.f;
    for (int k = lane * 4; k < N_DIM; k += 128) {
        __half2 h0 = *(const __half2*)(fb + k);
        __half2 h1 = *(const __half2*)(fb + k + 2);
        float4 wv = *(const float4*)(wr + k);
        acc += __half2float(h0.x) * wv.x + __half2float(h0.y) * wv.y
             + __half2float(h1.x) * wv.z + __half2float(h1.y) * wv.w;
    }
    #pragma unroll
    for (int o = 16; o > 0; o >>= 1) acc += __shfl_xor_sync(0xffffffffu, acc, o);
    if (lane == 0) out[b * 5 + w] = acc + bo[w];
}

// ------------------------------ launch -------------------------------------

extern "C" void kernel_launch(void* const* d_in, const int* in_sizes, int n_in,
                              void* d_out, int out_size) {
    (void)in_sizes; (void)n_in; (void)out_size;
    const float* x  = (const float*)d_in[0];
    const float* w1 = (const float*)d_in[1];
    const float* b1 = (const float*)d_in[2];
    const float* w2 = (const float*)d_in[3];
    const float* b2 = (const float*)d_in[4];
    const float* wl = (const float*)d_in[5];
    const float* bl = (const float*)d_in[6];
    const float* wo = (const float*)d_in[7];
    const float* bo = (const float*)d_in[8];
    float* out = (float*)d_out;

    __half *fa, *fb, *wh;
    cudaGetSymbolAddress((void**)&fa, g_act0);
    cudaGetSymbolAddress((void**)&fb, g_act1);
    cudaGetSymbolAddress((void**)&wh, g_wh);

    // fused frontend + weight conversion (+ pad-col zeroing)
    prep_kernel<<<FE_BLOCKS + CONV_BLOCKS, 128>>>(x, w1, b1, w2, b2, fa, fb, wl, wh);

    cudaFuncSetAttribute(gemm_relu_kernel,
                         cudaFuncAttributeMaxDynamicSharedMemorySize, SMEM_BYTES);
    dim3 grid((N_DIM + BN - 1) / BN, M_DIM / BM);   // (51, 16)
    gemm_relu_kernel<<<grid, 128, SMEM_BYTES>>>(fa, wh, bl, fb);
    gemm_relu_kernel<<<grid, 128, SMEM_BYTES>>>(fb, wh, bl, fa);
    gemm_relu_kernel<<<grid, 128, SMEM_BYTES>>>(fa, wh, bl, fb);
    gemm_relu_kernel<<<grid, 128, SMEM_BYTES>>>(fb, wh, bl, fa);

    head_kernel<<<2048, 160>>>(fa, wo, bo, out);
}

// round 12
// speedup vs baseline: 1.0350x; 1.0350x over previous
#include <cuda_runtime.h>
#include <cuda_fp16.h>
#include <cuda_bf16.h>
#include <cstdint>

// ---------------------------------------------------------------------------
// InversionModel R12: GEMM frozen from R11 (passing, ~71% of SIMT-HMMA peak).
// Frontend merged: ONE block per batch handles all 3 scales (hierarchical
// coarse-grain, weights register-resident across phases). GEMM grid swapped
// to mb-fastest for B-tile L2 reuse.
// ---------------------------------------------------------------------------

#define BM 128
#define BN 128
#define BK 64                  // halves per K tile
#define STAGES 3
#define ROWB 144               // smem bytes per row: 128 data + 16 pad
#define M_DIM 2048
#define N_DIM 6432
#define K_DIM 6432
#define KP    6464             // K padded: 101 * 64
#define STAGE_BYTES ((BM + BN) * ROWB)            // 36864
#define SMEM_BYTES  (STAGES * STAGE_BYTES)        // 110592

#define FE_BLOCKS 2048                            // one per batch
#define NWP ((long long)N_DIM * KP)               // padded weight elems
#define CONV_BLOCKS ((int)((NWP + 1023) / 1024))  // 128 thr x 8 elems

// Scratch (static device arrays; no allocation allowed)
__device__ __align__(16) __half g_act0[(size_t)M_DIM * KP];
__device__ __align__(16) __half g_act1[(size_t)M_DIM * KP];
__device__ __align__(16) __half g_wh[(size_t)N_DIM * KP];

// ------------------------------ helpers ------------------------------------

__device__ __forceinline__ void cp16(void* dst, const void* src, bool pred) {
    uint32_t s = (uint32_t)__cvta_generic_to_shared(dst);
    int sz = pred ? 16 : 0;
    asm volatile("cp.async.cg.shared.global [%0], [%1], 16, %2;\n"
                 :: "r"(s), "l"(src), "r"(sz));
}

__device__ __forceinline__ void mma16816(float* c, const uint32_t* a, const uint32_t* b) {
    asm volatile(
        "mma.sync.aligned.m16n8k16.row.col.f32.f16.f16.f32 "
        "{%0,%1,%2,%3}, {%4,%5,%6,%7}, {%8,%9}, {%0,%1,%2,%3};\n"
        : "+f"(c[0]), "+f"(c[1]), "+f"(c[2]), "+f"(c[3])
        : "r"(a[0]), "r"(a[1]), "r"(a[2]), "r"(a[3]), "r"(b[0]), "r"(b[1]));
}

__device__ __forceinline__ void ldsm4(uint32_t& r0, uint32_t& r1, uint32_t& r2,
                                      uint32_t& r3, uint32_t addr) {
    asm volatile("ldmatrix.sync.aligned.m8n8.x4.shared.b16 {%0,%1,%2,%3}, [%4];\n"
                 : "=r"(r0), "=r"(r1), "=r"(r2), "=r"(r3) : "r"(addr));
}

// ----------------- fused prep: merged frontend + weight convert -------------
// blocks [0, FE_BLOCKS)           : one batch, ALL 3 scales
// blocks [FE_BLOCKS, +CONV_BLOCKS): fp32->fp16 weight conversion into [N][KP]

__global__ void prep_kernel(const float* __restrict__ x,
                            const float* __restrict__ w1, const float* __restrict__ b1,
                            const float* __restrict__ w2, const float* __restrict__ b2,
                            __half* __restrict__ f, __half* __restrict__ f2,
                            const float* __restrict__ wl, __half* __restrict__ wh) {
    if (blockIdx.x >= FE_BLOCKS) {
        long long idx = (long long)(blockIdx.x - FE_BLOCKS) * 128 + threadIdx.x;
        const long long total = NWP / 8;
        if (idx < total) {
            int r  = (int)(idx / (KP / 8));
            int c0 = (int)(idx % (KP / 8)) * 8;
            uint4 outv = make_uint4(0, 0, 0, 0);
            if (c0 < K_DIM) {      // 6432 % 8 == 0: group fully in or fully pad
                const float* p = wl + (size_t)r * K_DIM + c0;
                float4 a = *(const float4*)p;
                float4 b = *(const float4*)(p + 4);
                __half2 h0 = __floats2half2_rn(a.x, a.y);
                __half2 h1 = __floats2half2_rn(a.z, a.w);
                __half2 h2 = __floats2half2_rn(b.x, b.y);
                __half2 h3 = __floats2half2_rn(b.z, b.w);
                outv = make_uint4(*(uint32_t*)&h0, *(uint32_t*)&h1,
                                  *(uint32_t*)&h2, *(uint32_t*)&h3);
            }
            *(uint4*)(wh + (size_t)r * KP + c0) = outv;
        }
        return;
    }

    int b = blockIdx.x;
    int tid = threadIdx.x;           // 128 threads

    __shared__ float xc1[4 * 480];
    __shared__ float xc2[4 * 240];
    __shared__ float xc4[4 * 120];
    __shared__ float p1[16 * 238 + 2];   // +2: harmless OOB window read guard
    __shared__ float w1s[320], w2s[2560];
    __shared__ float b1s[16], b2s[32];

    for (int i = tid; i < 320; i += 128) w1s[i] = w1[i];
    for (int i = tid; i < 2560; i += 128) w2s[i] = w2[i];
    if (tid < 16) b1s[tid] = b1[tid];
    if (tid < 32) b2s[tid] = b2[tid];

    // zero K-pad cols of both activation buffers
    if (tid < 32) {
        f [(size_t)b * KP + K_DIM + tid] = __float2half_rn(0.f);
        f2[(size_t)b * KP + K_DIM + tid] = __float2half_rn(0.f);
    }

    // load x (scale 1 IS x)
    const float* xb = x + (size_t)b * 1920;
    for (int i = tid; i < 1920; i += 128) xc1[i] = xb[i];
    __syncthreads();

    // hierarchical coarse grain: s=2 from s=1
    for (int i = tid; i < 960; i += 128) {
        int c = i / 240, p = i % 240;
        xc2[c * 240 + p] = 0.5f * (xc1[c * 480 + 2 * p] + xc1[c * 480 + 2 * p + 1]);
    }
    __syncthreads();
    // s=4 from s=2
    for (int i = tid; i < 480; i += 128) {
        int c = i / 120, p = i % 120;
        xc4[c * 120 + p] = 0.5f * (xc2[c * 240 + 2 * p] + xc2[c * 240 + 2 * p + 1]);
    }

    // register weights for this thread's channels (held across all phases)
    int o = tid & 15, ch = tid >> 4;          // conv1 mapping
    int o2 = tid & 31, ch2 = tid >> 5;        // conv2 mapping
    float w1r[20], w2r[80];
    #pragma unroll
    for (int i = 0; i < 20; ++i) w1r[i] = w1s[o * 20 + i];
    #pragma unroll
    for (int i = 0; i < 80; ++i) w2r[i] = w2s[o2 * 80 + i];
    float b1r = b1s[o], b2r = b2s[o2];
    __half* fb = f + (size_t)b * KP;

    #pragma unroll 1
    for (int sidx = 0; sidx < 3; ++sidx) {
        int Lc  = 480 >> sidx;
        int off = (sidx == 0) ? 0 : (sidx == 1 ? 117 : 174);
        const float* xcp = (sidx == 0) ? xc1 : (sidx == 1 ? xc2 : xc4);
        int L1p = (Lc - 4) >> 1;     // 238 / 118 / 58
        int L2  = (L1p - 4) >> 1;    // 117 / 57 / 27

        __syncthreads();             // xc ready; p1 free from previous phase

        // conv1 + relu + pool
        for (int q = ch; q < L1p; q += 8) {
            float a0 = b1r, a1 = b1r;
            #pragma unroll
            for (int c = 0; c < 4; ++c) {
                const float2* xp = (const float2*)&xcp[c * Lc + 2 * q];
                float2 v0 = xp[0], v1 = xp[1], v2 = xp[2];
                const float* w = &w1r[c * 5];
                a0 = fmaf(v0.x, w[0], a0);
                a0 = fmaf(v0.y, w[1], a0);
                a0 = fmaf(v1.x, w[2], a0);
                a0 = fmaf(v1.y, w[3], a0);
                a0 = fmaf(v2.x, w[4], a0);
                a1 = fmaf(v0.y, w[0], a1);
                a1 = fmaf(v1.x, w[1], a1);
                a1 = fmaf(v1.y, w[2], a1);
                a1 = fmaf(v2.x, w[3], a1);
                a1 = fmaf(v2.y, w[4], a1);
            }
            p1[o * L1p + q] = fmaxf(fmaxf(a0, a1), 0.f);
        }
        __syncthreads();

        // conv2 + relu + pool (q-pair window reuse, 4 chains)
        for (int q0 = 2 * ch2; q0 < L2; q0 += 8) {
            bool has2 = (q0 + 1) < L2;
            float a00 = b2r, a01 = b2r, a10 = b2r, a11 = b2r;
            #pragma unroll
            for (int c1 = 0; c1 < 16; ++c1) {
                const float2* pp = (const float2*)&p1[c1 * L1p + 2 * q0];
                float2 v0 = pp[0], v1 = pp[1], v2 = pp[2], v3 = pp[3];
                const float* w = &w2r[c1 * 5];
                a00 = fmaf(v0.x, w[0], a00);
                a00 = fmaf(v0.y, w[1], a00);
                a00 = fmaf(v1.x, w[2], a00);
                a00 = fmaf(v1.y, w[3], a00);
                a00 = fmaf(v2.x, w[4], a00);
                a01 = fmaf(v0.y, w[0], a01);
                a01 = fmaf(v1.x, w[1], a01);
                a01 = fmaf(v1.y, w[2], a01);
                a01 = fmaf(v2.x, w[3], a01);
                a01 = fmaf(v2.y, w[4], a01);
                a10 = fmaf(v1.x, w[0], a10);
                a10 = fmaf(v1.y, w[1], a10);
                a10 = fmaf(v2.x, w[2], a10);
                a10 = fmaf(v2.y, w[3], a10);
                a10 = fmaf(v3.x, w[4], a10);
                a11 = fmaf(v1.y, w[0], a11);
                a11 = fmaf(v2.x, w[1], a11);
                a11 = fmaf(v2.y, w[2], a11);
                a11 = fmaf(v3.x, w[3], a11);
                a11 = fmaf(v3.y, w[4], a11);
            }
            fb[o2 * 201 + off + q0] = __float2half_rn(fmaxf(fmaxf(a00, a01), 0.f));
            if (has2)
                fb[o2 * 201 + off + q0 + 1] = __float2half_rn(fmaxf(fmaxf(a10, a11), 0.f));
        }
    }
}

// ------------------------------- GEMM (frozen from R11) ---------------------
// 128x128x64 tiles, 4 warps (2x2), warp tile 64x64, 3 smem stages,
// ONE wait_group + __syncthreads per tile, all new-stage reads after it.

extern __shared__ __half dynsmem[];

__global__ __launch_bounds__(128, 2)
void gemm_relu_kernel(const __half* __restrict__ A, const __half* __restrict__ W,
                      const float* __restrict__ bias, __half* __restrict__ Out) {
    char* smem_c = (char*)dynsmem;

    const int tid = threadIdx.x;
    const int bm = blockIdx.x * BM;      // mb fastest: concurrent CTAs share B
    const int bn = blockIdx.y * BN;
    const int warp = tid >> 5, lane = tid & 31;
    const int wm = (warp >> 1) * 64;     // 0 or 64
    const int wn = (warp & 1) * 64;      // 0 or 64
    const int g = lane >> 2, tg = lane & 3;

    const int lr8 = tid >> 3;            // 0..15
    const int cbh = (tid & 7) * 8;       // halves offset 0..56

    const __half* Ag = A + (size_t)(bm + lr8) * KP + cbh;
    const __half* Wg = W + (size_t)(bn + lr8) * KP + cbh;
    const int limit = N_DIM - bn;
    bool bvm[8];
    #pragma unroll
    for (int i = 0; i < 8; ++i) bvm[i] = (lr8 + 16 * i) < limit;

#define LOAD_STAGE(slot, k0) do {                                             \
        char* _s  = smem_c + (slot) * STAGE_BYTES;                            \
        char* _sb = _s + BM * ROWB;                                           \
        _Pragma("unroll")                                                     \
        for (int _i = 0; _i < 8; ++_i)                                        \
            cp16(_s + (lr8 + 16 * _i) * ROWB + (cbh * 2),                     \
                 Ag + (size_t)(16 * _i) * KP + (k0), true);                   \
        _Pragma("unroll")                                                     \
        for (int _i = 0; _i < 8; ++_i)                                        \
            cp16(_sb + (lr8 + 16 * _i) * ROWB + (cbh * 2),                    \
                 Wg + (bvm[_i] ? (size_t)(16 * _i) * KP : 0) + (k0), bvm[_i]);\
    } while (0)

    const uint32_t sU = (uint32_t)__cvta_generic_to_shared(smem_c);
    const uint32_t a_off = (uint32_t)((wm + (lane & 15)) * ROWB + (lane >> 4) * 16);
    const uint32_t b_off = (uint32_t)(BM * ROWB
                                      + (wn + (lane >> 4) * 8 + (lane & 7)) * ROWB
                                      + ((lane >> 3) & 1) * 16);

#define LD_FRAGS(buf, ksb) do {                                                \
        _Pragma("unroll")                                                      \
        for (int _mt = 0; _mt < 4; ++_mt)                                      \
            ldsm4(afr[buf][_mt][0], afr[buf][_mt][1], afr[buf][_mt][2],        \
                  afr[buf][_mt][3], aS + (ksb) + _mt * 16 * ROWB);             \
        _Pragma("unroll")                                                      \
        for (int _p = 0; _p < 4; ++_p)                                         \
            ldsm4(bfr[buf][2 * _p][0], bfr[buf][2 * _p][1],                    \
                  bfr[buf][2 * _p + 1][0], bfr[buf][2 * _p + 1][1],            \
                  bS + (ksb) + _p * 16 * ROWB);                                \
    } while (0)

#define MMA_BATCH(buf) do {                                                    \
        _Pragma("unroll")                                                      \
        for (int _mt = 0; _mt < 4; ++_mt)                                      \
            _Pragma("unroll")                                                  \
            for (int _nt = 0; _nt < 8; ++_nt)                                  \
                mma16816(acc[_mt][_nt], afr[buf][_mt], bfr[buf][_nt]);         \
    } while (0)

    float acc[4][8][4];
    #pragma unroll
    for (int mt = 0; mt < 4; ++mt)
        #pragma unroll
        for (int nt = 0; nt < 8; ++nt)
            #pragma unroll
            for (int i = 0; i < 4; ++i) acc[mt][nt][i] = 0.f;

    uint32_t afr[2][4][4], bfr[2][8][2];

    // prologue: stages 0,1 hold tiles 0,1
    LOAD_STAGE(0, 0);
    asm volatile("cp.async.commit_group;\n");
    LOAD_STAGE(1, BK);
    asm volatile("cp.async.commit_group;\n");
    asm volatile("cp.async.wait_group 1;\n");
    __syncthreads();                            // ALL parts of tile 0 visible

    uint32_t aS = sU + a_off;                   // stage 0
    uint32_t bS = sU + b_off;
    LD_FRAGS(0, 0);                             // tile 0, ks0

    const int NT = KP / BK;   // 101
    int st = 0;
    #pragma unroll 1
    for (int kt = 0; kt < NT; ++kt) {
        LD_FRAGS(1, 32);      // ks1
        MMA_BATCH(0);         // ks0
        LD_FRAGS(0, 64);      // ks2
        MMA_BATCH(1);         // ks1
        LD_FRAGS(1, 96);      // ks3
        MMA_BATCH(0);         // ks2

        int knext = kt + 2;
        if (knext < NT) {
            int sl = st + 2; if (sl >= STAGES) sl -= STAGES;
            LOAD_STAGE(sl, knext * BK);
        }
        asm volatile("cp.async.commit_group;\n");

        MMA_BATCH(1);         // ks3 (no smem reads; overlaps wait below)

        asm volatile("cp.async.wait_group 1;\n");
        __syncthreads();                            // EVERYONE's tile kt+1 done

        int st1 = st + 1; if (st1 >= STAGES) st1 -= STAGES;
        aS = sU + (uint32_t)(st1 * STAGE_BYTES) + a_off;
        bS = sU + (uint32_t)(st1 * STAGE_BYTES) + b_off;
        LD_FRAGS(0, 0);       // next tile ks0 (garbage on last iter, unused)
        st = st1;
    }

    // Epilogue: bias + relu + fp16 store (row stride KP)
    #pragma unroll
    for (int mt = 0; mt < 4; ++mt) {
        int row = bm + wm + mt * 16 + g;
        #pragma unroll
        for (int nt = 0; nt < 8; ++nt) {
            int col = bn + wn + nt * 8 + tg * 2;
            if (col < N_DIM) {
                float2 bb = *(const float2*)(bias + col);
                float v0a = fmaxf(acc[mt][nt][0] + bb.x, 0.f);
                float v1a = fmaxf(acc[mt][nt][1] + bb.y, 0.f);
                float v2a = fmaxf(acc[mt][nt][2] + bb.x, 0.f);
                float v3a = fmaxf(acc[mt][nt][3] + bb.y, 0.f);
                *(__half2*)(Out + (size_t)row * KP + col)       = __floats2half2_rn(v0a, v1a);
                *(__half2*)(Out + (size_t)(row + 8) * KP + col) = __floats2half2_rn(v2a, v3a);
            }
        }
    }
#undef LOAD_STAGE
#undef LD_FRAGS
#undef MMA_BATCH
}

// ------------------------------- head --------------------------------------

__global__ void head_kernel(const __half* __restrict__ f, const float* __restrict__ wo,
                            const float* __restrict__ bo, float* __restrict__ out) {
    int b = blockIdx.x;
    int w = threadIdx.x >> 5;        // 0..4
    int lane = threadIdx.x & 31;
    const __half* fb = f + (size_t)b * KP;
    const float* wr = wo + (size_t)w * N_DIM;
    float acc = 0.f;
    for (int k = lane * 4; k < N_DIM; k += 128) {
        __half2 h0 = *(const __half2*)(fb + k);
        __half2 h1 = *(const __half2*)(fb + k + 2);
        float4 wv = *(const float4*)(wr + k);
        acc += __half2float(h0.x) * wv.x + __half2float(h0.y) * wv.y
             + __half2float(h1.x) * wv.z + __half2float(h1.y) * wv.w;
    }
    #pragma unroll
    for (int o = 16; o > 0; o >>= 1) acc += __shfl_xor_sync(0xffffffffu, acc, o);
    if (lane == 0) out[b * 5 + w] = acc + bo[w];
}

// ------------------------------ launch -------------------------------------

extern "C" void kernel_launch(void* const* d_in, const int* in_sizes, int n_in,
                              void* d_out, int out_size) {
    (void)in_sizes; (void)n_in; (void)out_size;
    const float* x  = (const float*)d_in[0];
    const float* w1 = (const float*)d_in[1];
    const float* b1 = (const float*)d_in[2];
    const float* w2 = (const float*)d_in[3];
    const float* b2 = (const float*)d_in[4];
    const float* wl = (const float*)d_in[5];
    const float* bl = (const float*)d_in[6];
    const float* wo = (const float*)d_in[7];
    const float* bo = (const float*)d_in[8];
    float* out = (float*)d_out;

    __half *fa, *fb, *wh;
    cudaGetSymbolAddress((void**)&fa, g_act0);
    cudaGetSymbolAddress((void**)&fb, g_act1);
    cudaGetSymbolAddress((void**)&wh, g_wh);

    // fused merged frontend + weight conversion (+ pad-col zeroing)
    prep_kernel<<<FE_BLOCKS + CONV_BLOCKS, 128>>>(x, w1, b1, w2, b2, fa, fb, wl, wh);

    cudaFuncSetAttribute(gemm_relu_kernel,
                         cudaFuncAttributeMaxDynamicSharedMemorySize, SMEM_BYTES);
    dim3 grid(M_DIM / BM, (N_DIM + BN - 1) / BN);   // (16, 51) mb-fastest
    gemm_relu_kernel<<<grid, 128, SMEM_BYTES>>>(fa, wh, bl, fb);
    gemm_relu_kernel<<<grid, 128, SMEM_BYTES>>>(fb, wh, bl, fa);
    gemm_relu_kernel<<<grid, 128, SMEM_BYTES>>>(fa, wh, bl, fb);
    gemm_relu_kernel<<<grid, 128, SMEM_BYTES>>>(fb, wh, bl, fa);

    head_kernel<<<2048, 160>>>(fa, wo, bo, out);
}

// round 13
// speedup vs baseline: 1.0361x; 1.0010x over previous
#include <cuda_runtime.h>
#include <cuda_fp16.h>
#include <cuda_bf16.h>
#include <cstdint>

// ---------------------------------------------------------------------------
// InversionModel R12: GEMM frozen from R11 (passing, ~71% of SIMT-HMMA peak).
// Frontend merged: ONE block per batch handles all 3 scales (hierarchical
// coarse-grain, weights register-resident across phases). GEMM grid swapped
// to mb-fastest for B-tile L2 reuse.
// ---------------------------------------------------------------------------

#define BM 128
#define BN 128
#define BK 64                  // halves per K tile
#define STAGES 3
#define ROWB 144               // smem bytes per row: 128 data + 16 pad
#define M_DIM 2048
#define N_DIM 6432
#define K_DIM 6432
#define KP    6464             // K padded: 101 * 64
#define STAGE_BYTES ((BM + BN) * ROWB)            // 36864
#define SMEM_BYTES  (STAGES * STAGE_BYTES)        // 110592

#define FE_BLOCKS 2048                            // one per batch
#define NWP ((long long)N_DIM * KP)               // padded weight elems
#define CONV_BLOCKS ((int)((NWP + 1023) / 1024))  // 128 thr x 8 elems

// Scratch (static device arrays; no allocation allowed)
__device__ __align__(16) __half g_act0[(size_t)M_DIM * KP];
__device__ __align__(16) __half g_act1[(size_t)M_DIM * KP];
__device__ __align__(16) __half g_wh[(size_t)N_DIM * KP];

// ------------------------------ helpers ------------------------------------

__device__ __forceinline__ void cp16(void* dst, const void* src, bool pred) {
    uint32_t s = (uint32_t)__cvta_generic_to_shared(dst);
    int sz = pred ? 16 : 0;
    asm volatile("cp.async.cg.shared.global [%0], [%1], 16, %2;\n"
                 :: "r"(s), "l"(src), "r"(sz));
}

__device__ __forceinline__ void mma16816(float* c, const uint32_t* a, const uint32_t* b) {
    asm volatile(
        "mma.sync.aligned.m16n8k16.row.col.f32.f16.f16.f32 "
        "{%0,%1,%2,%3}, {%4,%5,%6,%7}, {%8,%9}, {%0,%1,%2,%3};\n"
        : "+f"(c[0]), "+f"(c[1]), "+f"(c[2]), "+f"(c[3])
        : "r"(a[0]), "r"(a[1]), "r"(a[2]), "r"(a[3]), "r"(b[0]), "r"(b[1]));
}

__device__ __forceinline__ void ldsm4(uint32_t& r0, uint32_t& r1, uint32_t& r2,
                                      uint32_t& r3, uint32_t addr) {
    asm volatile("ldmatrix.sync.aligned.m8n8.x4.shared.b16 {%0,%1,%2,%3}, [%4];\n"
                 : "=r"(r0), "=r"(r1), "=r"(r2), "=r"(r3) : "r"(addr));
}

// ----------------- fused prep: merged frontend + weight convert -------------
// blocks [0, FE_BLOCKS)           : one batch, ALL 3 scales
// blocks [FE_BLOCKS, +CONV_BLOCKS): fp32->fp16 weight conversion into [N][KP]

__global__ void prep_kernel(const float* __restrict__ x,
                            const float* __restrict__ w1, const float* __restrict__ b1,
                            const float* __restrict__ w2, const float* __restrict__ b2,
                            __half* __restrict__ f, __half* __restrict__ f2,
                            const float* __restrict__ wl, __half* __restrict__ wh) {
    if (blockIdx.x >= FE_BLOCKS) {
        long long idx = (long long)(blockIdx.x - FE_BLOCKS) * 128 + threadIdx.x;
        const long long total = NWP / 8;
        if (idx < total) {
            int r  = (int)(idx / (KP / 8));
            int c0 = (int)(idx % (KP / 8)) * 8;
            uint4 outv = make_uint4(0, 0, 0, 0);
            if (c0 < K_DIM) {      // 6432 % 8 == 0: group fully in or fully pad
                const float* p = wl + (size_t)r * K_DIM + c0;
                float4 a = *(const float4*)p;
                float4 b = *(const float4*)(p + 4);
                __half2 h0 = __floats2half2_rn(a.x, a.y);
                __half2 h1 = __floats2half2_rn(a.z, a.w);
                __half2 h2 = __floats2half2_rn(b.x, b.y);
                __half2 h3 = __floats2half2_rn(b.z, b.w);
                outv = make_uint4(*(uint32_t*)&h0, *(uint32_t*)&h1,
                                  *(uint32_t*)&h2, *(uint32_t*)&h3);
            }
            *(uint4*)(wh + (size_t)r * KP + c0) = outv;
        }
        return;
    }

    int b = blockIdx.x;
    int tid = threadIdx.x;           // 128 threads

    __shared__ float xc1[4 * 480];
    __shared__ float xc2[4 * 240];
    __shared__ float xc4[4 * 120];
    __shared__ float p1[16 * 238 + 2];   // +2: harmless OOB window read guard
    __shared__ float w1s[320], w2s[2560];
    __shared__ float b1s[16], b2s[32];

    for (int i = tid; i < 320; i += 128) w1s[i] = w1[i];
    for (int i = tid; i < 2560; i += 128) w2s[i] = w2[i];
    if (tid < 16) b1s[tid] = b1[tid];
    if (tid < 32) b2s[tid] = b2[tid];

    // zero K-pad cols of both activation buffers
    if (tid < 32) {
        f [(size_t)b * KP + K_DIM + tid] = __float2half_rn(0.f);
        f2[(size_t)b * KP + K_DIM + tid] = __float2half_rn(0.f);
    }

    // load x (scale 1 IS x)
    const float* xb = x + (size_t)b * 1920;
    for (int i = tid; i < 1920; i += 128) xc1[i] = xb[i];
    __syncthreads();

    // hierarchical coarse grain: s=2 from s=1
    for (int i = tid; i < 960; i += 128) {
        int c = i / 240, p = i % 240;
        xc2[c * 240 + p] = 0.5f * (xc1[c * 480 + 2 * p] + xc1[c * 480 + 2 * p + 1]);
    }
    __syncthreads();
    // s=4 from s=2
    for (int i = tid; i < 480; i += 128) {
        int c = i / 120, p = i % 120;
        xc4[c * 120 + p] = 0.5f * (xc2[c * 240 + 2 * p] + xc2[c * 240 + 2 * p + 1]);
    }

    // register weights for this thread's channels (held across all phases)
    int o = tid & 15, ch = tid >> 4;          // conv1 mapping
    int o2 = tid & 31, ch2 = tid >> 5;        // conv2 mapping
    float w1r[20], w2r[80];
    #pragma unroll
    for (int i = 0; i < 20; ++i) w1r[i] = w1s[o * 20 + i];
    #pragma unroll
    for (int i = 0; i < 80; ++i) w2r[i] = w2s[o2 * 80 + i];
    float b1r = b1s[o], b2r = b2s[o2];
    __half* fb = f + (size_t)b * KP;

    #pragma unroll 1
    for (int sidx = 0; sidx < 3; ++sidx) {
        int Lc  = 480 >> sidx;
        int off = (sidx == 0) ? 0 : (sidx == 1 ? 117 : 174);
        const float* xcp = (sidx == 0) ? xc1 : (sidx == 1 ? xc2 : xc4);
        int L1p = (Lc - 4) >> 1;     // 238 / 118 / 58
        int L2  = (L1p - 4) >> 1;    // 117 / 57 / 27

        __syncthreads();             // xc ready; p1 free from previous phase

        // conv1 + relu + pool
        for (int q = ch; q < L1p; q += 8) {
            float a0 = b1r, a1 = b1r;
            #pragma unroll
            for (int c = 0; c < 4; ++c) {
                const float2* xp = (const float2*)&xcp[c * Lc + 2 * q];
                float2 v0 = xp[0], v1 = xp[1], v2 = xp[2];
                const float* w = &w1r[c * 5];
                a0 = fmaf(v0.x, w[0], a0);
                a0 = fmaf(v0.y, w[1], a0);
                a0 = fmaf(v1.x, w[2], a0);
                a0 = fmaf(v1.y, w[3], a0);
                a0 = fmaf(v2.x, w[4], a0);
                a1 = fmaf(v0.y, w[0], a1);
                a1 = fmaf(v1.x, w[1], a1);
                a1 = fmaf(v1.y, w[2], a1);
                a1 = fmaf(v2.x, w[3], a1);
                a1 = fmaf(v2.y, w[4], a1);
            }
            p1[o * L1p + q] = fmaxf(fmaxf(a0, a1), 0.f);
        }
        __syncthreads();

        // conv2 + relu + pool (q-pair window reuse, 4 chains)
        for (int q0 = 2 * ch2; q0 < L2; q0 += 8) {
            bool has2 = (q0 + 1) < L2;
            float a00 = b2r, a01 = b2r, a10 = b2r, a11 = b2r;
            #pragma unroll
            for (int c1 = 0; c1 < 16; ++c1) {
                const float2* pp = (const float2*)&p1[c1 * L1p + 2 * q0];
                float2 v0 = pp[0], v1 = pp[1], v2 = pp[2], v3 = pp[3];
                const float* w = &w2r[c1 * 5];
                a00 = fmaf(v0.x, w[0], a00);
                a00 = fmaf(v0.y, w[1], a00);
                a00 = fmaf(v1.x, w[2], a00);
                a00 = fmaf(v1.y, w[3], a00);
                a00 = fmaf(v2.x, w[4], a00);
                a01 = fmaf(v0.y, w[0], a01);
                a01 = fmaf(v1.x, w[1], a01);
                a01 = fmaf(v1.y, w[2], a01);
                a01 = fmaf(v2.x, w[3], a01);
                a01 = fmaf(v2.y, w[4], a01);
                a10 = fmaf(v1.x, w[0], a10);
                a10 = fmaf(v1.y, w[1], a10);
                a10 = fmaf(v2.x, w[2], a10);
                a10 = fmaf(v2.y, w[3], a10);
                a10 = fmaf(v3.x, w[4], a10);
                a11 = fmaf(v1.y, w[0], a11);
                a11 = fmaf(v2.x, w[1], a11);
                a11 = fmaf(v2.y, w[2], a11);
                a11 = fmaf(v3.x, w[3], a11);
                a11 = fmaf(v3.y, w[4], a11);
            }
            fb[o2 * 201 + off + q0] = __float2half_rn(fmaxf(fmaxf(a00, a01), 0.f));
            if (has2)
                fb[o2 * 201 + off + q0 + 1] = __float2half_rn(fmaxf(fmaxf(a10, a11), 0.f));
        }
    }
}

// ------------------------------- GEMM (frozen from R11) ---------------------
// 128x128x64 tiles, 4 warps (2x2), warp tile 64x64, 3 smem stages,
// ONE wait_group + __syncthreads per tile, all new-stage reads after it.

extern __shared__ __half dynsmem[];

__global__ __launch_bounds__(128, 2)
void gemm_relu_kernel(const __half* __restrict__ A, const __half* __restrict__ W,
                      const float* __restrict__ bias, __half* __restrict__ Out) {
    char* smem_c = (char*)dynsmem;

    const int tid = threadIdx.x;
    const int bm = blockIdx.x * BM;      // mb fastest: concurrent CTAs share B
    const int bn = blockIdx.y * BN;
    const int warp = tid >> 5, lane = tid & 31;
    const int wm = (warp >> 1) * 64;     // 0 or 64
    const int wn = (warp & 1) * 64;      // 0 or 64
    const int g = lane >> 2, tg = lane & 3;

    const int lr8 = tid >> 3;            // 0..15
    const int cbh = (tid & 7) * 8;       // halves offset 0..56

    const __half* Ag = A + (size_t)(bm + lr8) * KP + cbh;
    const __half* Wg = W + (size_t)(bn + lr8) * KP + cbh;
    const int limit = N_DIM - bn;
    bool bvm[8];
    #pragma unroll
    for (int i = 0; i < 8; ++i) bvm[i] = (lr8 + 16 * i) < limit;

#define LOAD_STAGE(slot, k0) do {                                             \
        char* _s  = smem_c + (slot) * STAGE_BYTES;                            \
        char* _sb = _s + BM * ROWB;                                           \
        _Pragma("unroll")                                                     \
        for (int _i = 0; _i < 8; ++_i)                                        \
            cp16(_s + (lr8 + 16 * _i) * ROWB + (cbh * 2),                     \
                 Ag + (size_t)(16 * _i) * KP + (k0), true);                   \
        _Pragma("unroll")                                                     \
        for (int _i = 0; _i < 8; ++_i)                                        \
            cp16(_sb + (lr8 + 16 * _i) * ROWB + (cbh * 2),                    \
                 Wg + (bvm[_i] ? (size_t)(16 * _i) * KP : 0) + (k0), bvm[_i]);\
    } while (0)

    const uint32_t sU = (uint32_t)__cvta_generic_to_shared(smem_c);
    const uint32_t a_off = (uint32_t)((wm + (lane & 15)) * ROWB + (lane >> 4) * 16);
    const uint32_t b_off = (uint32_t)(BM * ROWB
                                      + (wn + (lane >> 4) * 8 + (lane & 7)) * ROWB
                                      + ((lane >> 3) & 1) * 16);

#define LD_FRAGS(buf, ksb) do {                                                \
        _Pragma("unroll")                                                      \
        for (int _mt = 0; _mt < 4; ++_mt)                                      \
            ldsm4(afr[buf][_mt][0], afr[buf][_mt][1], afr[buf][_mt][2],        \
                  afr[buf][_mt][3], aS + (ksb) + _mt * 16 * ROWB);             \
        _Pragma("unroll")                                                      \
        for (int _p = 0; _p < 4; ++_p)                                         \
            ldsm4(bfr[buf][2 * _p][0], bfr[buf][2 * _p][1],                    \
                  bfr[buf][2 * _p + 1][0], bfr[buf][2 * _p + 1][1],            \
                  bS + (ksb) + _p * 16 * ROWB);                                \
    } while (0)

#define MMA_BATCH(buf) do {                                                    \
        _Pragma("unroll")                                                      \
        for (int _mt = 0; _mt < 4; ++_mt)                                      \
            _Pragma("unroll")                                                  \
            for (int _nt = 0; _nt < 8; ++_nt)                                  \
                mma16816(acc[_mt][_nt], afr[buf][_mt], bfr[buf][_nt]);         \
    } while (0)

    float acc[4][8][4];
    #pragma unroll
    for (int mt = 0; mt < 4; ++mt)
        #pragma unroll
        for (int nt = 0; nt < 8; ++nt)
            #pragma unroll
            for (int i = 0; i < 4; ++i) acc[mt][nt][i] = 0.f;

    uint32_t afr[2][4][4], bfr[2][8][2];

    // prologue: stages 0,1 hold tiles 0,1
    LOAD_STAGE(0, 0);
    asm volatile("cp.async.commit_group;\n");
    LOAD_STAGE(1, BK);
    asm volatile("cp.async.commit_group;\n");
    asm volatile("cp.async.wait_group 1;\n");
    __syncthreads();                            // ALL parts of tile 0 visible

    uint32_t aS = sU + a_off;                   // stage 0
    uint32_t bS = sU + b_off;
    LD_FRAGS(0, 0);                             // tile 0, ks0

    const int NT = KP / BK;   // 101
    int st = 0;
    #pragma unroll 1
    for (int kt = 0; kt < NT; ++kt) {
        LD_FRAGS(1, 32);      // ks1
        MMA_BATCH(0);         // ks0
        LD_FRAGS(0, 64);      // ks2
        MMA_BATCH(1);         // ks1
        LD_FRAGS(1, 96);      // ks3
        MMA_BATCH(0);         // ks2

        int knext = kt + 2;
        if (knext < NT) {
            int sl = st + 2; if (sl >= STAGES) sl -= STAGES;
            LOAD_STAGE(sl, knext * BK);
        }
        asm volatile("cp.async.commit_group;\n");

        MMA_BATCH(1);         // ks3 (no smem reads; overlaps wait below)

        asm volatile("cp.async.wait_group 1;\n");
        __syncthreads();                            // EVERYONE's tile kt+1 done

        int st1 = st + 1; if (st1 >= STAGES) st1 -= STAGES;
        aS = sU + (uint32_t)(st1 * STAGE_BYTES) + a_off;
        bS = sU + (uint32_t)(st1 * STAGE_BYTES) + b_off;
        LD_FRAGS(0, 0);       // next tile ks0 (garbage on last iter, unused)
        st = st1;
    }

    // Epilogue: bias + relu + fp16 store (row stride KP)
    #pragma unroll
    for (int mt = 0; mt < 4; ++mt) {
        int row = bm + wm + mt * 16 + g;
        #pragma unroll
        for (int nt = 0; nt < 8; ++nt) {
            int col = bn + wn + nt * 8 + tg * 2;
            if (col < N_DIM) {
                float2 bb = *(const float2*)(bias + col);
                float v0a = fmaxf(acc[mt][nt][0] + bb.x, 0.f);
                float v1a = fmaxf(acc[mt][nt][1] + bb.y, 0.f);
                float v2a = fmaxf(acc[mt][nt][2] + bb.x, 0.f);
                float v3a = fmaxf(acc[mt][nt][3] + bb.y, 0.f);
                *(__half2*)(Out + (size_t)row * KP + col)       = __floats2half2_rn(v0a, v1a);
                *(__half2*)(Out + (size_t)(row + 8) * KP + col) = __floats2half2_rn(v2a, v3a);
            }
        }
    }
#undef LOAD_STAGE
#undef LD_FRAGS
#undef MMA_BATCH
}

// ------------------------------- head --------------------------------------

__global__ void head_kernel(const __half* __restrict__ f, const float* __restrict__ wo,
                            const float* __restrict__ bo, float* __restrict__ out) {
    int b = blockIdx.x;
    int w = threadIdx.x >> 5;        // 0..4
    int lane = threadIdx.x & 31;
    const __half* fb = f + (size_t)b * KP;
    const float* wr = wo + (size_t)w * N_DIM;
    float acc = 0.f;
    for (int k = lane * 4; k < N_DIM; k += 128) {
        __half2 h0 = *(const __half2*)(fb + k);
        __half2 h1 = *(const __half2*)(fb + k + 2);
        float4 wv = *(const float4*)(wr + k);
        acc += __half2float(h0.x) * wv.x + __half2float(h0.y) * wv.y
             + __half2float(h1.x) * wv.z + __half2float(h1.y) * wv.w;
    }
    #pragma unroll
    for (int o = 16; o > 0; o >>= 1) acc += __shfl_xor_sync(0xffffffffu, acc, o);
    if (lane == 0) out[b * 5 + w] = acc + bo[w];
}

// ------------------------------ launch -------------------------------------

extern "C" void kernel_launch(void* const* d_in, const int* in_sizes, int n_in,
                              void* d_out, int out_size) {
    (void)in_sizes; (void)n_in; (void)out_size;
    const float* x  = (const float*)d_in[0];
    const float* w1 = (const float*)d_in[1];
    const float* b1 = (const float*)d_in[2];
    const float* w2 = (const float*)d_in[3];
    const float* b2 = (const float*)d_in[4];
    const float* wl = (const float*)d_in[5];
    const float* bl = (const float*)d_in[6];
    const float* wo = (const float*)d_in[7];
    const float* bo = (const float*)d_in[8];
    float* out = (float*)d_out;

    __half *fa, *fb, *wh;
    cudaGetSymbolAddress((void**)&fa, g_act0);
    cudaGetSymbolAddress((void**)&fb, g_act1);
    cudaGetSymbolAddress((void**)&wh, g_wh);

    // fused merged frontend + weight conversion (+ pad-col zeroing)
    prep_kernel<<<FE_BLOCKS + CONV_BLOCKS, 128>>>(x, w1, b1, w2, b2, fa, fb, wl, wh);

    cudaFuncSetAttribute(gemm_relu_kernel,
                         cudaFuncAttributeMaxDynamicSharedMemorySize, SMEM_BYTES);
    dim3 grid(M_DIM / BM, (N_DIM + BN - 1) / BN);   // (16, 51) mb-fastest
    gemm_relu_kernel<<<grid, 128, SMEM_BYTES>>>(fa, wh, bl, fb);
    gemm_relu_kernel<<<grid, 128, SMEM_BYTES>>>(fb, wh, bl, fa);
    gemm_relu_kernel<<<grid, 128, SMEM_BYTES>>>(fa, wh, bl, fb);
    gemm_relu_kernel<<<grid, 128, SMEM_BYTES>>>(fb, wh, bl, fa);

    head_kernel<<<2048, 160>>>(fa, wo, bo, out);
}